// round 14
// baseline (speedup 1.0000x reference)
#include <cuda_runtime.h>
#include <cstdint>

#define TT    131072
#define INW   60
#define HH    14
#define CHUNK 64
#define WARM  32
#define NCH   (TT / CHUNK)     // 2048
#define TB    128              // xproj timesteps per block
#define FULLM 0xFFFFFFFFu

// Scratch (static __device__ — no allocation per harness rules)
// pad 448 floats: prefetch reaches ~2 rows past TT
__device__ float g_xw0s[TT * 56 + 448];

__device__ __forceinline__ float tanh_ap(float x) {
    float r; asm("tanh.approx.f32 %0, %1;" : "=f"(r) : "f"(x)); return r;
}
// Packed 2-wide FMA / ADD (sm_100+): ptxas never emits these from C++, only via PTX.
__device__ __forceinline__ float2 ffma2(float2 a, float2 b, float2 c) {
    union { float2 f; unsigned long long u; } ua, ub, uc, ud;
    ua.f = a; ub.f = b; uc.f = c;
    asm("fma.rn.f32x2 %0, %1, %2, %3;" : "=l"(ud.u) : "l"(ua.u), "l"(ub.u), "l"(uc.u));
    return ud.f;
}
__device__ __forceinline__ float2 fadd2(float2 a, float2 b) {
    union { float2 f; unsigned long long u; } ua, ub, uc;
    ua.f = a; ub.f = b;
    asm("add.rn.f32x2 %0, %1, %2;" : "=l"(uc.u) : "l"(ua.u), "l"(ub.u));
    return uc.f;
}

// ---------------- Kernel 1: xw0 = x @ W_ih0^T + b_ih0 ----------------
// Known-good 256-thread, 2-pass version (R12): lane tile 2t x 7g.
__global__ void __launch_bounds__(256, 3)
xproj_kernel(const float* __restrict__ x,
             const float* __restrict__ W,
             const float* __restrict__ b) {
    __shared__ float2 sX[TB][31];    // [t][kp], pad 31: conflict-free
    __shared__ float2 sW[56][31];    // [j][kp]
    __shared__ float  sB[56];

    const int tid = threadIdx.x;
    const int t0  = blockIdx.x * TB;

    const float2* Wg = (const float2*)W;             // rows of 30 float2
    for (int idx = tid; idx < 56 * 30; idx += 256) {
        int jj = idx / 30, kp = idx - jj * 30;
        sW[jj][kp] = Wg[idx];
    }
    if (tid < 56) sB[tid] = b[tid];
    const float2* Xg = (const float2*)(x + t0 * INW);  // 8B-aligned (240B rows)
    for (int idx = tid; idx < TB * 30; idx += 256) {
        int t = idx / 30, kp = idx - t * 30;
        sX[t][kp] = Xg[idx];
    }
    __syncthreads();

#pragma unroll
    for (int p = 0; p < 2; p++) {
        const int tile = tid + p * 256;      // 0..511
        const int jb = (tile & 7) * 7;       // gate base (7 gates)
        const int tb = (tile >> 3) * 2;      // timestep base (2 steps)

        float2 acc[2][7];
#pragma unroll
        for (int i = 0; i < 2; i++)
#pragma unroll
            for (int q = 0; q < 7; q++)
                acc[i][q] = make_float2(sB[jb + q], 0.f);

#pragma unroll 6
        for (int kp = 0; kp < 30; kp++) {
            float2 xv0 = sX[tb][kp];
            float2 xv1 = sX[tb + 1][kp];
#pragma unroll
            for (int q = 0; q < 7; q++) {
                float2 wv = sW[jb + q][kp];
                acc[0][q] = ffma2(xv0, wv, acc[0][q]);
                acc[1][q] = ffma2(xv1, wv, acc[1][q]);
            }
        }

        float* dst0 = g_xw0s + (t0 + tb) * 56 + jb;
        float* dst1 = dst0 + 56;
#pragma unroll
        for (int q = 0; q < 7; q++) {
            dst0[q] = acc[0][q].x + acc[0][q].y;
            dst1[q] = acc[1][q].x + acc[1][q].y;
        }
    }
}

// ---------------- Scan helpers ----------------
// All activations via MUFU.TANH (measured error contribution ~1e-6).
__device__ __forceinline__ float act_h(float a, float q, float& c, int kidx,
                                       float kq2, float mm2, float aa2) {
    float sA = fmaf(tanh_ap(a * 0.5f), 0.5f, 0.5f);      // sigmoid (i/f)
    float sQ = fmaf(tanh_ap(q * kq2), mm2, aa2);         // tanh(g) | sigmoid(o)
    float iv = __shfl_sync(FULLM, sA, kidx);
    float fv = __shfl_sync(FULLM, sA, kidx + 14);
    float gv = __shfl_sync(FULLM, sQ, kidx);
    float ov = __shfl_sync(FULLM, sQ, kidx + 14);
    c = fmaf(fv, c, iv * gv);
    return ov * tanh_ap(c);
}

__device__ __forceinline__ void bcast(float2 (&hp)[7], float hn) {
#pragma unroll
    for (int k = 0; k < 7; k++) {
        hp[k].x = __shfl_sync(FULLM, hn, 2 * k);
        hp[k].y = __shfl_sync(FULLM, hn, 2 * k + 1);
    }
}

// ---------------- Kernel 2: chunk-parallel LSTM scan, smem L1/L2 weights ----------------
// Block = 1 warp = 1 chunk of CHUNK=64 steps; grid 2048 -> ~13.8 blocks/SM.
// launch_bounds(32,14) forces regs <= 146 so all 2048 fit in ONE wave at 2x
// the warp residency of R13 (which was grid-bound at 6.9 blocks/SM).
// The four L1/L2 weight matrices (112 regs) live in per-block smem
// (one-time 12.25KB load; 56 conflict-free LDS.64/iter with static addresses).
// Whh0 + Wlin + all state stay in registers. WARM=32 warmup from (h,c)=0.
__global__ void __launch_bounds__(32, 14)
lstm_scan_kernel(const float* __restrict__ h0in, const float* __restrict__ c0in,
                 const float* __restrict__ Whh0, const float* __restrict__ bhh0,
                 const float* __restrict__ Wih1, const float* __restrict__ Whh1,
                 const float* __restrict__ bih1, const float* __restrict__ bhh1,
                 const float* __restrict__ Wih2, const float* __restrict__ Whh2,
                 const float* __restrict__ bih2, const float* __restrict__ bhh2,
                 const float* __restrict__ Wlin, const float* __restrict__ blin,
                 float* __restrict__ gout) {
    // planes: 0:w1iA 1:w1iQ 2:w1hA 3:w1hQ 4:w2iA 5:w2iQ 6:w2hA 7:w2hQ
    __shared__ float2 sw[8][7][28];

    const int chunk = blockIdx.x;
    const int t0 = chunk * CHUNK;
    const int te = t0 + CHUNK;
    const int s  = (chunk == 0) ? 0 : (t0 - WARM);

    const int  j    = threadIdx.x;
    const int  jj   = (j < 28) ? j : 27;
    const int  kidx = j % 14;
    const bool isg  = (j < 14);
    const float kq2 = isg ? 1.0f : 0.5f;
    const float mm2 = isg ? 1.0f : 0.5f;
    const float aa2 = isg ? 0.0f : 0.5f;

    // one-time: stage L1/L2 weights into smem (lanes 0..27)
    if (j < 28) {
        const float* Wsrc[4] = {Wih1, Whh1, Wih2, Whh2};
#pragma unroll
        for (int m = 0; m < 4; m++) {
#pragma unroll
            for (int k = 0; k < 7; k++) {
                sw[2 * m][k][j]     = *(const float2*)&Wsrc[m][j * HH + 2 * k];
                sw[2 * m + 1][k][j] = *(const float2*)&Wsrc[m][(j + 28) * HH + 2 * k];
            }
        }
    }
    __syncwarp();

    // L0 weights in registers
    float2 w0A[7], w0Q[7];
#pragma unroll
    for (int k = 0; k < 7; k++) {
        w0A[k] = *(const float2*)&Whh0[jj * HH + 2 * k];
        w0Q[k] = *(const float2*)&Whh0[(jj + 28) * HH + 2 * k];
    }
    const float b0A = bhh0[jj],            b0Q = bhh0[jj + 28];
    const float b1A = bih1[jj] + bhh1[jj], b1Q = bih1[jj + 28] + bhh1[jj + 28];
    const float b2A = bih2[jj] + bhh2[jj], b2Q = bih2[jj + 28] + bhh2[jj + 28];

    // fused output projection: lane o = j%7 holds Wlin row o
    const int olane = j % 7;
    float2 wl[7];
#pragma unroll
    for (int k = 0; k < 7; k++) wl[k] = *(const float2*)&Wlin[olane * HH + 2 * k];
    const float blv = blin[olane];

    // state: packed replicated h per layer, distributed c
    float2 h0p[7], h1p[7], h2p[7];
    float c0v, c1v, c2v;
    if (chunk == 0) {
#pragma unroll
        for (int k = 0; k < 7; k++) {
            h0p[k] = *(const float2*)&h0in[2 * k];
            h1p[k] = *(const float2*)&h0in[HH + 2 * k];
            h2p[k] = *(const float2*)&h0in[2 * HH + 2 * k];
        }
        c0v = c0in[kidx]; c1v = c0in[HH + kidx]; c2v = c0in[2 * HH + kidx];
    } else {
#pragma unroll
        for (int k = 0; k < 7; k++) {
            h0p[k] = make_float2(0.f, 0.f);
            h1p[k] = make_float2(0.f, 0.f);
            h2p[k] = make_float2(0.f, 0.f);
        }
        c0v = c1v = c2v = 0.f;
    }

    auto do_L0 = [&](float xA, float xQ) -> float {
        float2 aA = make_float2(b0A + xA, 0.f), aQ = make_float2(b0Q + xQ, 0.f);
#pragma unroll
        for (int k = 0; k < 7; k++) {
            aA = ffma2(h0p[k], w0A[k], aA);
            aQ = ffma2(h0p[k], w0Q[k], aQ);
        }
        return act_h(aA.x + aA.y, aQ.x + aQ.y, c0v, kidx, kq2, mm2, aa2);
    };
    auto do_L1 = [&]() -> float {
        float2 aAi = make_float2(b1A, 0.f), aQi = make_float2(b1Q, 0.f);
        float2 aAh = make_float2(0.f, 0.f), aQh = make_float2(0.f, 0.f);
#pragma unroll
        for (int k = 0; k < 7; k++) {
            aAi = ffma2(h0p[k], sw[0][k][jj], aAi);
            aQi = ffma2(h0p[k], sw[1][k][jj], aQi);
            aAh = ffma2(h1p[k], sw[2][k][jj], aAh);
            aQh = ffma2(h1p[k], sw[3][k][jj], aQh);
        }
        float2 aA = fadd2(aAi, aAh), aQ = fadd2(aQi, aQh);
        return act_h(aA.x + aA.y, aQ.x + aQ.y, c1v, kidx, kq2, mm2, aa2);
    };
    auto do_L2 = [&]() -> float {
        float2 aAi = make_float2(b2A, 0.f), aQi = make_float2(b2Q, 0.f);
        float2 aAh = make_float2(0.f, 0.f), aQh = make_float2(0.f, 0.f);
#pragma unroll
        for (int k = 0; k < 7; k++) {
            aAi = ffma2(h1p[k], sw[4][k][jj], aAi);
            aQi = ffma2(h1p[k], sw[5][k][jj], aQi);
            aAh = ffma2(h2p[k], sw[6][k][jj], aAh);
            aQh = ffma2(h2p[k], sw[7][k][jj], aQh);
        }
        float2 aA = fadd2(aAi, aAh), aQ = fadd2(aQi, aQh);
        return act_h(aA.x + aA.y, aQ.x + aQ.y, c2v, kidx, kq2, mm2, aa2);
    };
    // out(t) = relu(relu(h2(t)) @ Wlin^T + blin); h2p must hold replicated h2(t)
    auto do_out = [&](int t) {
        float2 acc = make_float2(blv, 0.f);
#pragma unroll
        for (int k = 0; k < 7; k++) {
            float2 hv = make_float2(fmaxf(h2p[k].x, 0.f), fmaxf(h2p[k].y, 0.f));
            acc = ffma2(hv, wl[k], acc);
        }
        float o = fmaxf(acc.x + acc.y, 0.f);
        if (j < 7) gout[t * 7 + j] = o;
    };

    // one full pipelined iteration at step i; out(i-3) uses h2p BEFORE updates
    auto body = [&](int i, float xA, float xQ) {
        if (i - 3 >= t0) do_out(i - 3);
        float hn0 = do_L0(xA, xQ);
        float hn1 = do_L1();
        float hn2 = do_L2();
        bcast(h0p, hn0);
        bcast(h1p, hn1);
        bcast(h2p, hn2);
    };

    int i = s;

    // ---- Phase A: 2 fill iterations ----
    if (chunk == 0) {
        float xA0 = g_xw0s[jj],      xQ0 = g_xw0s[jj + 28];
        float xA1 = g_xw0s[56 + jj], xQ1 = g_xw0s[56 + jj + 28];
        { float hn0 = do_L0(xA0, xQ0); bcast(h0p, hn0); }
        { float hn1 = do_L1();
          float hn0 = do_L0(xA1, xQ1);
          bcast(h0p, hn0); bcast(h1p, hn1); }
        i = 2;
    } else {
        float xA0 = g_xw0s[s * 56 + jj],        xQ0 = g_xw0s[s * 56 + jj + 28];
        float xA1 = g_xw0s[(s + 1) * 56 + jj],  xQ1 = g_xw0s[(s + 1) * 56 + jj + 28];
        body(i, xA0, xQ0);       // i-3 < t0: no out-store
        body(i + 1, xA1, xQ1);
        i = s + 2;
    }

    // ---- prime the 2-deep x FIFO for steps i, i+1 ----
    float xbA[2], xbQ[2];
#pragma unroll
    for (int u = 0; u < 2; u++) {
        xbA[u] = g_xw0s[(i + u) * 56 + jj];
        xbQ[u] = g_xw0s[(i + u) * 56 + jj + 28];
    }

    // ---- main loop: unrolled x2, prefetch distance 2 (body count is even) ----
#pragma unroll 1
    for (; i + 2 <= te; i += 2) {
#pragma unroll
        for (int u = 0; u < 2; u++) {
            float xA = xbA[u], xQ = xbQ[u];
            xbA[u] = g_xw0s[(i + u + 2) * 56 + jj];        // prefetch i+u+2
            xbQ[u] = g_xw0s[(i + u + 2) * 56 + jj + 28];
            body(i + u, xA, xQ);
        }
    }

    // ---- epilogues: drain L1, L2, out (state lives in registers) ----
    {   // out(te-3), L1(te-1), L2(te-2)
        do_out(te - 3);
        float hn1 = do_L1();
        float hn2 = do_L2();
        bcast(h1p, hn1);
        bcast(h2p, hn2);
    }
    {   // out(te-2), L2(te-1)
        do_out(te - 2);
        float hn2 = do_L2();
        bcast(h2p, hn2);
    }
    {   // out(te-1)
        do_out(te - 1);
    }
}

extern "C" void kernel_launch(void* const* d_in, const int* in_sizes, int n_in,
                              void* d_out, int out_size) {
    const float* x    = (const float*)d_in[0];
    const float* h0   = (const float*)d_in[1];
    const float* c0   = (const float*)d_in[2];
    const float* Wih0 = (const float*)d_in[3];
    const float* Whh0 = (const float*)d_in[4];
    const float* bih0 = (const float*)d_in[5];
    const float* bhh0 = (const float*)d_in[6];
    const float* Wih1 = (const float*)d_in[7];
    const float* Whh1 = (const float*)d_in[8];
    const float* bih1 = (const float*)d_in[9];
    const float* bhh1 = (const float*)d_in[10];
    const float* Wih2 = (const float*)d_in[11];
    const float* Whh2 = (const float*)d_in[12];
    const float* bih2 = (const float*)d_in[13];
    const float* bhh2 = (const float*)d_in[14];
    const float* Wlin = (const float*)d_in[15];
    const float* blin = (const float*)d_in[16];
    float* out = (float*)d_out;

    xproj_kernel<<<TT / TB, 256>>>(x, Wih0, bih0);
    lstm_scan_kernel<<<NCH, 32>>>(h0, c0, Whh0, bhh0,
                                  Wih1, Whh1, bih1, bhh1,
                                  Wih2, Whh2, bih2, bhh2,
                                  Wlin, blin, out);
}

// round 15
// speedup vs baseline: 2.7202x; 2.7202x over previous
#include <cuda_runtime.h>
#include <cstdint>

#define TT    131072
#define INW   60
#define HH    14
#define CHUNK 128
#define WARM  32
#define NCH   (TT / CHUNK)     // 1024
#define TB    128              // xproj timesteps per block
#define FULLM 0xFFFFFFFFu

// Scratch (static __device__ — no allocation per harness rules)
// pad 448 floats: steady loop prefetches up to (te+3)*56+55
__device__ float g_xw0s[TT * 56 + 448];

__device__ __forceinline__ float tanh_ap(float x) {
    float r; asm("tanh.approx.f32 %0, %1;" : "=f"(r) : "f"(x)); return r;
}
// Packed 2-wide FMA / ADD (sm_100+): ptxas never emits these from C++, only via PTX.
__device__ __forceinline__ float2 ffma2(float2 a, float2 b, float2 c) {
    union { float2 f; unsigned long long u; } ua, ub, uc, ud;
    ua.f = a; ub.f = b; uc.f = c;
    asm("fma.rn.f32x2 %0, %1, %2, %3;" : "=l"(ud.u) : "l"(ua.u), "l"(ub.u), "l"(uc.u));
    return ud.f;
}
__device__ __forceinline__ float2 fadd2(float2 a, float2 b) {
    union { float2 f; unsigned long long u; } ua, ub, uc;
    ua.f = a; ub.f = b;
    asm("add.rn.f32x2 %0, %1, %2;" : "=l"(uc.u) : "l"(ua.u), "l"(ub.u));
    return uc.f;
}

// ---------------- Kernel 1: xw0 = x @ W_ih0^T + b_ih0 ----------------
// Known-good 256-thread, 2-pass version: lane tile 2t x 7g.
__global__ void __launch_bounds__(256, 3)
xproj_kernel(const float* __restrict__ x,
             const float* __restrict__ W,
             const float* __restrict__ b) {
    __shared__ float2 sX[TB][31];    // [t][kp], pad 31: conflict-free
    __shared__ float2 sW[56][31];    // [j][kp]
    __shared__ float  sB[56];

    const int tid = threadIdx.x;
    const int t0  = blockIdx.x * TB;

    const float2* Wg = (const float2*)W;             // rows of 30 float2
    for (int idx = tid; idx < 56 * 30; idx += 256) {
        int jj = idx / 30, kp = idx - jj * 30;
        sW[jj][kp] = Wg[idx];
    }
    if (tid < 56) sB[tid] = b[tid];
    const float2* Xg = (const float2*)(x + t0 * INW);  // 8B-aligned (240B rows)
    for (int idx = tid; idx < TB * 30; idx += 256) {
        int t = idx / 30, kp = idx - t * 30;
        sX[t][kp] = Xg[idx];
    }
    __syncthreads();

#pragma unroll
    for (int p = 0; p < 2; p++) {
        const int tile = tid + p * 256;      // 0..511
        const int jb = (tile & 7) * 7;       // gate base (7 gates)
        const int tb = (tile >> 3) * 2;      // timestep base (2 steps)

        float2 acc[2][7];
#pragma unroll
        for (int i = 0; i < 2; i++)
#pragma unroll
            for (int q = 0; q < 7; q++)
                acc[i][q] = make_float2(sB[jb + q], 0.f);

#pragma unroll 6
        for (int kp = 0; kp < 30; kp++) {
            float2 xv0 = sX[tb][kp];
            float2 xv1 = sX[tb + 1][kp];
#pragma unroll
            for (int q = 0; q < 7; q++) {
                float2 wv = sW[jb + q][kp];
                acc[0][q] = ffma2(xv0, wv, acc[0][q]);
                acc[1][q] = ffma2(xv1, wv, acc[1][q]);
            }
        }

        float* dst0 = g_xw0s + (t0 + tb) * 56 + jb;
        float* dst1 = dst0 + 56;
#pragma unroll
        for (int q = 0; q < 7; q++) {
            dst0[q] = acc[0][q].x + acc[0][q].y;
            dst1[q] = acc[1][q].x + acc[1][q].y;
        }
    }
}

// ---------------- Scan helpers ----------------
__device__ __forceinline__ void mv7(float2& accA, float2& accQ,
                                    const float2 (&wA)[7], const float2 (&wQ)[7],
                                    const float2 (&hp)[7]) {
#pragma unroll
    for (int k = 0; k < 7; k++) {
        accA = ffma2(hp[k], wA[k], accA);
        accQ = ffma2(hp[k], wQ[k], accQ);
    }
}

// All activations via MUFU.TANH (measured error contribution ~1e-6).
__device__ __forceinline__ float act_h(float a, float q, float& c, int kidx,
                                       float kq2, float mm2, float aa2) {
    float sA = fmaf(tanh_ap(a * 0.5f), 0.5f, 0.5f);      // sigmoid (i/f)
    float sQ = fmaf(tanh_ap(q * kq2), mm2, aa2);         // tanh(g) | sigmoid(o)
    float iv = __shfl_sync(FULLM, sA, kidx);
    float fv = __shfl_sync(FULLM, sA, kidx + 14);
    float gv = __shfl_sync(FULLM, sQ, kidx);
    float ov = __shfl_sync(FULLM, sQ, kidx + 14);
    c = fmaf(fv, c, iv * gv);
    return ov * tanh_ap(c);
}

__device__ __forceinline__ void bcast(float2 (&hp)[7], float hn) {
#pragma unroll
    for (int k = 0; k < 7; k++) {
        hp[k].x = __shfl_sync(FULLM, hn, 2 * k);
        hp[k].y = __shfl_sync(FULLM, hn, 2 * k + 1);
    }
}

// ---------------- Kernel 2: chunk-parallel 3-layer LSTM scan + fused output proj ----------------
// R13's proven configuration (74.5us measured): block = 1 warp = 1 chunk of
// CHUNK=128; 1024 blocks = one resident wave at 246 regs (8 blocks/SM cap).
// Chunks > 0 start WARM=32 early from (h,c)=0 (forget-gate contraction).
// ALL weights in registers (R14 proved a reg cap just converts regs to L2
// spill traffic: 292us). h broadcast via SHFL; x via 4-deep FIFO; out fused.
__global__ void __launch_bounds__(32)
lstm_scan_kernel(const float* __restrict__ h0in, const float* __restrict__ c0in,
                 const float* __restrict__ Whh0, const float* __restrict__ bhh0,
                 const float* __restrict__ Wih1, const float* __restrict__ Whh1,
                 const float* __restrict__ bih1, const float* __restrict__ bhh1,
                 const float* __restrict__ Wih2, const float* __restrict__ Whh2,
                 const float* __restrict__ bih2, const float* __restrict__ bhh2,
                 const float* __restrict__ Wlin, const float* __restrict__ blin,
                 float* __restrict__ gout) {
    const int chunk = blockIdx.x;
    const int t0 = chunk * CHUNK;
    const int te = t0 + CHUNK;
    const int s  = (chunk == 0) ? 0 : (t0 - WARM);

    const int  j    = threadIdx.x;
    const int  jj   = (j < 28) ? j : 27;
    const int  kidx = j % 14;
    const bool isg  = (j < 14);
    const float kq2 = isg ? 1.0f : 0.5f;
    const float mm2 = isg ? 1.0f : 0.5f;
    const float aa2 = isg ? 0.0f : 0.5f;

    // weights in registers, packed (w[j][2k], w[j][2k+1])
    float2 w0A[7],  w0Q[7];
    float2 w1iA[7], w1iQ[7], w1hA[7], w1hQ[7];
    float2 w2iA[7], w2iQ[7], w2hA[7], w2hQ[7];
#pragma unroll
    for (int k = 0; k < 7; k++) {
        w0A[k]  = *(const float2*)&Whh0[jj * HH + 2 * k];
        w0Q[k]  = *(const float2*)&Whh0[(jj + 28) * HH + 2 * k];
        w1iA[k] = *(const float2*)&Wih1[jj * HH + 2 * k];
        w1iQ[k] = *(const float2*)&Wih1[(jj + 28) * HH + 2 * k];
        w1hA[k] = *(const float2*)&Whh1[jj * HH + 2 * k];
        w1hQ[k] = *(const float2*)&Whh1[(jj + 28) * HH + 2 * k];
        w2iA[k] = *(const float2*)&Wih2[jj * HH + 2 * k];
        w2iQ[k] = *(const float2*)&Wih2[(jj + 28) * HH + 2 * k];
        w2hA[k] = *(const float2*)&Whh2[jj * HH + 2 * k];
        w2hQ[k] = *(const float2*)&Whh2[(jj + 28) * HH + 2 * k];
    }
    const float b0A = bhh0[jj],            b0Q = bhh0[jj + 28];
    const float b1A = bih1[jj] + bhh1[jj], b1Q = bih1[jj + 28] + bhh1[jj + 28];
    const float b2A = bih2[jj] + bhh2[jj], b2Q = bih2[jj + 28] + bhh2[jj + 28];

    // fused output projection: lane o = j%7 holds Wlin row o
    const int olane = j % 7;
    float2 wl[7];
#pragma unroll
    for (int k = 0; k < 7; k++) wl[k] = *(const float2*)&Wlin[olane * HH + 2 * k];
    const float blv = blin[olane];

    // state: packed replicated h per layer, distributed c
    float2 h0p[7], h1p[7], h2p[7];
    float c0v, c1v, c2v;
    if (chunk == 0) {
#pragma unroll
        for (int k = 0; k < 7; k++) {
            h0p[k] = *(const float2*)&h0in[2 * k];
            h1p[k] = *(const float2*)&h0in[HH + 2 * k];
            h2p[k] = *(const float2*)&h0in[2 * HH + 2 * k];
        }
        c0v = c0in[kidx]; c1v = c0in[HH + kidx]; c2v = c0in[2 * HH + kidx];
    } else {
#pragma unroll
        for (int k = 0; k < 7; k++) {
            h0p[k] = make_float2(0.f, 0.f);
            h1p[k] = make_float2(0.f, 0.f);
            h2p[k] = make_float2(0.f, 0.f);
        }
        c0v = c1v = c2v = 0.f;
    }

    auto do_L0 = [&](float xA, float xQ) -> float {
        float2 aA = make_float2(b0A + xA, 0.f), aQ = make_float2(b0Q + xQ, 0.f);
        mv7(aA, aQ, w0A, w0Q, h0p);
        return act_h(aA.x + aA.y, aQ.x + aQ.y, c0v, kidx, kq2, mm2, aa2);
    };
    auto do_L1 = [&]() -> float {
        float2 aAi = make_float2(b1A, 0.f), aQi = make_float2(b1Q, 0.f);
        float2 aAh = make_float2(0.f, 0.f), aQh = make_float2(0.f, 0.f);
        mv7(aAi, aQi, w1iA, w1iQ, h0p);
        mv7(aAh, aQh, w1hA, w1hQ, h1p);
        float2 aA = fadd2(aAi, aAh), aQ = fadd2(aQi, aQh);
        return act_h(aA.x + aA.y, aQ.x + aQ.y, c1v, kidx, kq2, mm2, aa2);
    };
    auto do_L2 = [&]() -> float {
        float2 aAi = make_float2(b2A, 0.f), aQi = make_float2(b2Q, 0.f);
        float2 aAh = make_float2(0.f, 0.f), aQh = make_float2(0.f, 0.f);
        mv7(aAi, aQi, w2iA, w2iQ, h1p);
        mv7(aAh, aQh, w2hA, w2hQ, h2p);
        float2 aA = fadd2(aAi, aAh), aQ = fadd2(aQi, aQh);
        return act_h(aA.x + aA.y, aQ.x + aQ.y, c2v, kidx, kq2, mm2, aa2);
    };
    // out(t) = relu(relu(h2(t)) @ Wlin^T + blin); h2p must hold replicated h2(t)
    auto do_out = [&](int t) {
        float2 acc = make_float2(blv, 0.f);
#pragma unroll
        for (int k = 0; k < 7; k++) {
            float2 hv = make_float2(fmaxf(h2p[k].x, 0.f), fmaxf(h2p[k].y, 0.f));
            acc = ffma2(hv, wl[k], acc);
        }
        float o = fmaxf(acc.x + acc.y, 0.f);
        if (j < 7) gout[t * 7 + j] = o;
    };

    // one full pipelined iteration at step i; out(i-3) uses h2p BEFORE updates
    auto body = [&](int i, float xA, float xQ) {
        if (i - 3 >= t0) do_out(i - 3);
        float hn0 = do_L0(xA, xQ);
        float hn1 = do_L1();
        float hn2 = do_L2();
        bcast(h0p, hn0);
        bcast(h1p, hn1);
        bcast(h2p, hn2);
    };

    int i = s;

    // ---- Phase A: 2 fill iterations ----
    if (chunk == 0) {
        float xA0 = g_xw0s[jj],      xQ0 = g_xw0s[jj + 28];
        float xA1 = g_xw0s[56 + jj], xQ1 = g_xw0s[56 + jj + 28];
        { float hn0 = do_L0(xA0, xQ0); bcast(h0p, hn0); }
        { float hn1 = do_L1();
          float hn0 = do_L0(xA1, xQ1);
          bcast(h0p, hn0); bcast(h1p, hn1); }
        i = 2;
    } else {
        float xA0 = g_xw0s[s * 56 + jj],        xQ0 = g_xw0s[s * 56 + jj + 28];
        float xA1 = g_xw0s[(s + 1) * 56 + jj],  xQ1 = g_xw0s[(s + 1) * 56 + jj + 28];
        body(i, xA0, xQ0);       // i-3 < t0: no out-store
        body(i + 1, xA1, xQ1);
        i = s + 2;
    }

    // ---- prime the 4-deep x FIFO for steps i..i+3 ----
    float xbA[4], xbQ[4];
#pragma unroll
    for (int u = 0; u < 4; u++) {
        xbA[u] = g_xw0s[(i + u) * 56 + jj];
        xbQ[u] = g_xw0s[(i + u) * 56 + jj + 28];
    }

    // ---- main loop: unrolled x4, prefetch distance 4 ----
#pragma unroll 1
    for (; i + 4 <= te; i += 4) {
#pragma unroll
        for (int u = 0; u < 4; u++) {
            float xA = xbA[u], xQ = xbQ[u];
            xbA[u] = g_xw0s[(i + u + 4) * 56 + jj];        // prefetch i+u+4
            xbQ[u] = g_xw0s[(i + u + 4) * 56 + jj + 28];
            body(i + u, xA, xQ);
        }
    }
    // remainder (<= 3 iters)
#pragma unroll 3
    for (int u = 0; i < te; i++, u++) {
        body(i, xbA[u], xbQ[u]);
    }

    // ---- epilogues: drain L1, L2, out (state lives in registers) ----
    {   // out(te-3), L1(te-1), L2(te-2)
        do_out(te - 3);
        float hn1 = do_L1();
        float hn2 = do_L2();
        bcast(h1p, hn1);
        bcast(h2p, hn2);
    }
    {   // out(te-2), L2(te-1)
        do_out(te - 2);
        float hn2 = do_L2();
        bcast(h2p, hn2);
    }
    {   // out(te-1)
        do_out(te - 1);
    }
}

extern "C" void kernel_launch(void* const* d_in, const int* in_sizes, int n_in,
                              void* d_out, int out_size) {
    const float* x    = (const float*)d_in[0];
    const float* h0   = (const float*)d_in[1];
    const float* c0   = (const float*)d_in[2];
    const float* Wih0 = (const float*)d_in[3];
    const float* Whh0 = (const float*)d_in[4];
    const float* bih0 = (const float*)d_in[5];
    const float* bhh0 = (const float*)d_in[6];
    const float* Wih1 = (const float*)d_in[7];
    const float* Whh1 = (const float*)d_in[8];
    const float* bih1 = (const float*)d_in[9];
    const float* bhh1 = (const float*)d_in[10];
    const float* Wih2 = (const float*)d_in[11];
    const float* Whh2 = (const float*)d_in[12];
    const float* bih2 = (const float*)d_in[13];
    const float* bhh2 = (const float*)d_in[14];
    const float* Wlin = (const float*)d_in[15];
    const float* blin = (const float*)d_in[16];
    float* out = (float*)d_out;

    xproj_kernel<<<TT / TB, 256>>>(x, Wih0, bih0);
    lstm_scan_kernel<<<NCH, 32>>>(h0, c0, Whh0, bhh0,
                                  Wih1, Whh1, bih1, bhh1,
                                  Wih2, Whh2, bih2, bhh2,
                                  Wlin, blin, out);
}

// round 16
// speedup vs baseline: 2.9197x; 1.0733x over previous
#include <cuda_runtime.h>
#include <cstdint>

#define TT    131072
#define INW   60
#define HH    14
#define CHUNK 128
#define WARM  32
#define NCH   (TT / CHUNK)     // 1024
#define TB    128              // xproj timesteps per block
#define FULLM 0xFFFFFFFFu

// Scratch (static __device__ — no allocation per harness rules)
// pad 448 floats: steady loop prefetches up to (te+3)*56+55
__device__ float g_xw0s[TT * 56 + 448];

__device__ __forceinline__ float tanh_ap(float x) {
    float r; asm("tanh.approx.f32 %0, %1;" : "=f"(r) : "f"(x)); return r;
}
// Packed 2-wide FMA / ADD (sm_100+): ptxas never emits these from C++, only via PTX.
__device__ __forceinline__ float2 ffma2(float2 a, float2 b, float2 c) {
    union { float2 f; unsigned long long u; } ua, ub, uc, ud;
    ua.f = a; ub.f = b; uc.f = c;
    asm("fma.rn.f32x2 %0, %1, %2, %3;" : "=l"(ud.u) : "l"(ua.u), "l"(ub.u), "l"(uc.u));
    return ud.f;
}
__device__ __forceinline__ float2 fadd2(float2 a, float2 b) {
    union { float2 f; unsigned long long u; } ua, ub, uc;
    ua.f = a; ub.f = b;
    asm("add.rn.f32x2 %0, %1, %2;" : "=l"(uc.u) : "l"(ua.u), "l"(ub.u));
    return uc.f;
}

// ---------------- Kernel 1: xw0 = x @ W_ih0^T + b_ih0 ----------------
// LDS-bytes-bound analysis: bytes/ffma2 = 8*(1/t_tile + 1/(2*j_tile)).
// 2t x 7g measured ~30us (1.0GB LDS). This version: 4t x 7g one-pass
// (2.57 B/ffma2, 0.57GB) with 256 threads = exactly 256 tiles, reg cap 85
// via launch_bounds(256,3) -> 24 warps/SM (enough to saturate LDS BW).
__global__ void __launch_bounds__(256, 3)
xproj_kernel(const float* __restrict__ x,
             const float* __restrict__ W,
             const float* __restrict__ b) {
    __shared__ float2 sX[TB][31];    // [t][kp], pad 31: conflict-free
    __shared__ float2 sW[56][31];    // [j][kp]
    __shared__ float  sB[56];

    const int tid = threadIdx.x;
    const int t0  = blockIdx.x * TB;

    const float2* Wg = (const float2*)W;             // rows of 30 float2
    for (int idx = tid; idx < 56 * 30; idx += 256) {
        int jj = idx / 30, kp = idx - jj * 30;
        sW[jj][kp] = Wg[idx];
    }
    if (tid < 56) sB[tid] = b[tid];
    const float2* Xg = (const float2*)(x + t0 * INW);  // 8B-aligned (240B rows)
    for (int idx = tid; idx < TB * 30; idx += 256) {
        int t = idx / 30, kp = idx - t * 30;
        sX[t][kp] = Xg[idx];
    }
    __syncthreads();

    const int jb = (tid & 7) * 7;        // gate base (7 gates)
    const int tb = (tid >> 3) * 4;       // timestep base (4 steps)

    float2 acc[4][7];
#pragma unroll
    for (int i = 0; i < 4; i++)
#pragma unroll
        for (int q = 0; q < 7; q++)
            acc[i][q] = make_float2(sB[jb + q], 0.f);

#pragma unroll 5
    for (int kp = 0; kp < 30; kp++) {
        float2 xv0 = sX[tb][kp];
        float2 xv1 = sX[tb + 1][kp];
        float2 xv2 = sX[tb + 2][kp];
        float2 xv3 = sX[tb + 3][kp];
#pragma unroll
        for (int q = 0; q < 7; q++) {
            float2 wv = sW[jb + q][kp];
            acc[0][q] = ffma2(xv0, wv, acc[0][q]);
            acc[1][q] = ffma2(xv1, wv, acc[1][q]);
            acc[2][q] = ffma2(xv2, wv, acc[2][q]);
            acc[3][q] = ffma2(xv3, wv, acc[3][q]);
        }
    }

#pragma unroll
    for (int i = 0; i < 4; i++) {
        float* dst = g_xw0s + (t0 + tb + i) * 56 + jb;
#pragma unroll
        for (int q = 0; q < 7; q++)
            dst[q] = acc[i][q].x + acc[i][q].y;
    }
}

// ---------------- Scan helpers ----------------
__device__ __forceinline__ void mv7(float2& accA, float2& accQ,
                                    const float2 (&wA)[7], const float2 (&wQ)[7],
                                    const float2 (&hp)[7]) {
#pragma unroll
    for (int k = 0; k < 7; k++) {
        accA = ffma2(hp[k], wA[k], accA);
        accQ = ffma2(hp[k], wQ[k], accQ);
    }
}

// All activations via MUFU.TANH (measured error contribution ~1e-6).
__device__ __forceinline__ float act_h(float a, float q, float& c, int kidx,
                                       float kq2, float mm2, float aa2) {
    float sA = fmaf(tanh_ap(a * 0.5f), 0.5f, 0.5f);      // sigmoid (i/f)
    float sQ = fmaf(tanh_ap(q * kq2), mm2, aa2);         // tanh(g) | sigmoid(o)
    float iv = __shfl_sync(FULLM, sA, kidx);
    float fv = __shfl_sync(FULLM, sA, kidx + 14);
    float gv = __shfl_sync(FULLM, sQ, kidx);
    float ov = __shfl_sync(FULLM, sQ, kidx + 14);
    c = fmaf(fv, c, iv * gv);
    return ov * tanh_ap(c);
}

__device__ __forceinline__ void bcast(float2 (&hp)[7], float hn) {
#pragma unroll
    for (int k = 0; k < 7; k++) {
        hp[k].x = __shfl_sync(FULLM, hn, 2 * k);
        hp[k].y = __shfl_sync(FULLM, hn, 2 * k + 1);
    }
}

// ---------------- Kernel 2: chunk-parallel 3-layer LSTM scan + fused output proj ----------------
// Proven configuration (74.2us measured): block = 1 warp = 1 chunk of
// CHUNK=128; 1024 blocks = one resident wave at 246 regs (8 blocks/SM cap).
// Chunks > 0 start WARM=32 early from (h,c)=0 (forget-gate contraction).
// ALL weights in registers (R14 proved a reg cap just converts regs to L2
// spill traffic). h broadcast via SHFL; x via 4-deep FIFO; out fused.
__global__ void __launch_bounds__(32)
lstm_scan_kernel(const float* __restrict__ h0in, const float* __restrict__ c0in,
                 const float* __restrict__ Whh0, const float* __restrict__ bhh0,
                 const float* __restrict__ Wih1, const float* __restrict__ Whh1,
                 const float* __restrict__ bih1, const float* __restrict__ bhh1,
                 const float* __restrict__ Wih2, const float* __restrict__ Whh2,
                 const float* __restrict__ bih2, const float* __restrict__ bhh2,
                 const float* __restrict__ Wlin, const float* __restrict__ blin,
                 float* __restrict__ gout) {
    const int chunk = blockIdx.x;
    const int t0 = chunk * CHUNK;
    const int te = t0 + CHUNK;
    const int s  = (chunk == 0) ? 0 : (t0 - WARM);

    const int  j    = threadIdx.x;
    const int  jj   = (j < 28) ? j : 27;
    const int  kidx = j % 14;
    const bool isg  = (j < 14);
    const float kq2 = isg ? 1.0f : 0.5f;
    const float mm2 = isg ? 1.0f : 0.5f;
    const float aa2 = isg ? 0.0f : 0.5f;

    // weights in registers, packed (w[j][2k], w[j][2k+1])
    float2 w0A[7],  w0Q[7];
    float2 w1iA[7], w1iQ[7], w1hA[7], w1hQ[7];
    float2 w2iA[7], w2iQ[7], w2hA[7], w2hQ[7];
#pragma unroll
    for (int k = 0; k < 7; k++) {
        w0A[k]  = *(const float2*)&Whh0[jj * HH + 2 * k];
        w0Q[k]  = *(const float2*)&Whh0[(jj + 28) * HH + 2 * k];
        w1iA[k] = *(const float2*)&Wih1[jj * HH + 2 * k];
        w1iQ[k] = *(const float2*)&Wih1[(jj + 28) * HH + 2 * k];
        w1hA[k] = *(const float2*)&Whh1[jj * HH + 2 * k];
        w1hQ[k] = *(const float2*)&Whh1[(jj + 28) * HH + 2 * k];
        w2iA[k] = *(const float2*)&Wih2[jj * HH + 2 * k];
        w2iQ[k] = *(const float2*)&Wih2[(jj + 28) * HH + 2 * k];
        w2hA[k] = *(const float2*)&Whh2[jj * HH + 2 * k];
        w2hQ[k] = *(const float2*)&Whh2[(jj + 28) * HH + 2 * k];
    }
    const float b0A = bhh0[jj],            b0Q = bhh0[jj + 28];
    const float b1A = bih1[jj] + bhh1[jj], b1Q = bih1[jj + 28] + bhh1[jj + 28];
    const float b2A = bih2[jj] + bhh2[jj], b2Q = bih2[jj + 28] + bhh2[jj + 28];

    // fused output projection: lane o = j%7 holds Wlin row o
    const int olane = j % 7;
    float2 wl[7];
#pragma unroll
    for (int k = 0; k < 7; k++) wl[k] = *(const float2*)&Wlin[olane * HH + 2 * k];
    const float blv = blin[olane];

    // state: packed replicated h per layer, distributed c
    float2 h0p[7], h1p[7], h2p[7];
    float c0v, c1v, c2v;
    if (chunk == 0) {
#pragma unroll
        for (int k = 0; k < 7; k++) {
            h0p[k] = *(const float2*)&h0in[2 * k];
            h1p[k] = *(const float2*)&h0in[HH + 2 * k];
            h2p[k] = *(const float2*)&h0in[2 * HH + 2 * k];
        }
        c0v = c0in[kidx]; c1v = c0in[HH + kidx]; c2v = c0in[2 * HH + kidx];
    } else {
#pragma unroll
        for (int k = 0; k < 7; k++) {
            h0p[k] = make_float2(0.f, 0.f);
            h1p[k] = make_float2(0.f, 0.f);
            h2p[k] = make_float2(0.f, 0.f);
        }
        c0v = c1v = c2v = 0.f;
    }

    auto do_L0 = [&](float xA, float xQ) -> float {
        float2 aA = make_float2(b0A + xA, 0.f), aQ = make_float2(b0Q + xQ, 0.f);
        mv7(aA, aQ, w0A, w0Q, h0p);
        return act_h(aA.x + aA.y, aQ.x + aQ.y, c0v, kidx, kq2, mm2, aa2);
    };
    auto do_L1 = [&]() -> float {
        float2 aAi = make_float2(b1A, 0.f), aQi = make_float2(b1Q, 0.f);
        float2 aAh = make_float2(0.f, 0.f), aQh = make_float2(0.f, 0.f);
        mv7(aAi, aQi, w1iA, w1iQ, h0p);
        mv7(aAh, aQh, w1hA, w1hQ, h1p);
        float2 aA = fadd2(aAi, aAh), aQ = fadd2(aQi, aQh);
        return act_h(aA.x + aA.y, aQ.x + aQ.y, c1v, kidx, kq2, mm2, aa2);
    };
    auto do_L2 = [&]() -> float {
        float2 aAi = make_float2(b2A, 0.f), aQi = make_float2(b2Q, 0.f);
        float2 aAh = make_float2(0.f, 0.f), aQh = make_float2(0.f, 0.f);
        mv7(aAi, aQi, w2iA, w2iQ, h1p);
        mv7(aAh, aQh, w2hA, w2hQ, h2p);
        float2 aA = fadd2(aAi, aAh), aQ = fadd2(aQi, aQh);
        return act_h(aA.x + aA.y, aQ.x + aQ.y, c2v, kidx, kq2, mm2, aa2);
    };
    // out(t) = relu(relu(h2(t)) @ Wlin^T + blin); h2p must hold replicated h2(t)
    auto do_out = [&](int t) {
        float2 acc = make_float2(blv, 0.f);
#pragma unroll
        for (int k = 0; k < 7; k++) {
            float2 hv = make_float2(fmaxf(h2p[k].x, 0.f), fmaxf(h2p[k].y, 0.f));
            acc = ffma2(hv, wl[k], acc);
        }
        float o = fmaxf(acc.x + acc.y, 0.f);
        if (j < 7) gout[t * 7 + j] = o;
    };

    // one full pipelined iteration at step i; out(i-3) uses h2p BEFORE updates
    auto body = [&](int i, float xA, float xQ) {
        if (i - 3 >= t0) do_out(i - 3);
        float hn0 = do_L0(xA, xQ);
        float hn1 = do_L1();
        float hn2 = do_L2();
        bcast(h0p, hn0);
        bcast(h1p, hn1);
        bcast(h2p, hn2);
    };

    int i = s;

    // ---- Phase A: 2 fill iterations ----
    if (chunk == 0) {
        float xA0 = g_xw0s[jj],      xQ0 = g_xw0s[jj + 28];
        float xA1 = g_xw0s[56 + jj], xQ1 = g_xw0s[56 + jj + 28];
        { float hn0 = do_L0(xA0, xQ0); bcast(h0p, hn0); }
        { float hn1 = do_L1();
          float hn0 = do_L0(xA1, xQ1);
          bcast(h0p, hn0); bcast(h1p, hn1); }
        i = 2;
    } else {
        float xA0 = g_xw0s[s * 56 + jj],        xQ0 = g_xw0s[s * 56 + jj + 28];
        float xA1 = g_xw0s[(s + 1) * 56 + jj],  xQ1 = g_xw0s[(s + 1) * 56 + jj + 28];
        body(i, xA0, xQ0);       // i-3 < t0: no out-store
        body(i + 1, xA1, xQ1);
        i = s + 2;
    }

    // ---- prime the 4-deep x FIFO for steps i..i+3 ----
    float xbA[4], xbQ[4];
#pragma unroll
    for (int u = 0; u < 4; u++) {
        xbA[u] = g_xw0s[(i + u) * 56 + jj];
        xbQ[u] = g_xw0s[(i + u) * 56 + jj + 28];
    }

    // ---- main loop: unrolled x4, prefetch distance 4 ----
#pragma unroll 1
    for (; i + 4 <= te; i += 4) {
#pragma unroll
        for (int u = 0; u < 4; u++) {
            float xA = xbA[u], xQ = xbQ[u];
            xbA[u] = g_xw0s[(i + u + 4) * 56 + jj];        // prefetch i+u+4
            xbQ[u] = g_xw0s[(i + u + 4) * 56 + jj + 28];
            body(i + u, xA, xQ);
        }
    }
    // remainder (<= 3 iters)
#pragma unroll 3
    for (int u = 0; i < te; i++, u++) {
        body(i, xbA[u], xbQ[u]);
    }

    // ---- epilogues: drain L1, L2, out (state lives in registers) ----
    {   // out(te-3), L1(te-1), L2(te-2)
        do_out(te - 3);
        float hn1 = do_L1();
        float hn2 = do_L2();
        bcast(h1p, hn1);
        bcast(h2p, hn2);
    }
    {   // out(te-2), L2(te-1)
        do_out(te - 2);
        float hn2 = do_L2();
        bcast(h2p, hn2);
    }
    {   // out(te-1)
        do_out(te - 1);
    }
}

extern "C" void kernel_launch(void* const* d_in, const int* in_sizes, int n_in,
                              void* d_out, int out_size) {
    const float* x    = (const float*)d_in[0];
    const float* h0   = (const float*)d_in[1];
    const float* c0   = (const float*)d_in[2];
    const float* Wih0 = (const float*)d_in[3];
    const float* Whh0 = (const float*)d_in[4];
    const float* bih0 = (const float*)d_in[5];
    const float* bhh0 = (const float*)d_in[6];
    const float* Wih1 = (const float*)d_in[7];
    const float* Whh1 = (const float*)d_in[8];
    const float* bih1 = (const float*)d_in[9];
    const float* bhh1 = (const float*)d_in[10];
    const float* Wih2 = (const float*)d_in[11];
    const float* Whh2 = (const float*)d_in[12];
    const float* bih2 = (const float*)d_in[13];
    const float* bhh2 = (const float*)d_in[14];
    const float* Wlin = (const float*)d_in[15];
    const float* blin = (const float*)d_in[16];
    float* out = (float*)d_out;

    xproj_kernel<<<TT / TB, 256>>>(x, Wih0, bih0);
    lstm_scan_kernel<<<NCH, 32>>>(h0, c0, Whh0, bhh0,
                                  Wih1, Whh1, bih1, bhh1,
                                  Wih2, Whh2, bih2, bhh2,
                                  Wlin, blin, out);
}

// round 17
// speedup vs baseline: 3.2056x; 1.0979x over previous
#include <cuda_runtime.h>
#include <cstdint>

#define TT    131072
#define INW   60
#define HH    14
#define CHUNK 128
#define WARM  32
#define NCH   (TT / CHUNK)     // 1024
#define TB    128              // xproj timesteps per block
#define FULLM 0xFFFFFFFFu

// Scratch (static __device__ — no allocation per harness rules)
// pad 448 floats: steady loop prefetches up to (te+3)*56+55
__device__ float g_xw0s[TT * 56 + 448];

__device__ __forceinline__ float tanh_ap(float x) {
    float r; asm("tanh.approx.f32 %0, %1;" : "=f"(r) : "f"(x)); return r;
}
// Packed 2-wide FMA / ADD (sm_100+): ptxas never emits these from C++, only via PTX.
__device__ __forceinline__ float2 ffma2(float2 a, float2 b, float2 c) {
    union { float2 f; unsigned long long u; } ua, ub, uc, ud;
    ua.f = a; ub.f = b; uc.f = c;
    asm("fma.rn.f32x2 %0, %1, %2, %3;" : "=l"(ud.u) : "l"(ua.u), "l"(ub.u), "l"(uc.u));
    return ud.f;
}
__device__ __forceinline__ float2 fadd2(float2 a, float2 b) {
    union { float2 f; unsigned long long u; } ua, ub, uc;
    ua.f = a; ub.f = b;
    asm("add.rn.f32x2 %0, %1, %2;" : "=l"(uc.u) : "l"(ua.u), "l"(ub.u));
    return uc.f;
}

// ---------------- Kernel 1: xw0 = x @ W_ih0^T + b_ih0 ----------------
// LDS-bytes model: bytes/lane-ffma2 = 8*(1/t_tile + 1/(2*j_tile)).
// 8t x 7g tile (1.57 B/ffma2) -> LDS bound ~10us; FMA bound ~12.5us dominates.
// 128-thread blocks: 16 t-groups x 8 gate-groups = 128 tiles exactly; ~150 regs
// -> 3 blocks/SM (12 warps) with NO aggressive cap (R14 lesson: caps = spills).
// Rows interleaved (row = tg + 16*i) so the 4 distinct x-addresses per warp hit
// distinct bank-pairs (conflict-free LDS.64).
__global__ void __launch_bounds__(128)
xproj_kernel(const float* __restrict__ x,
             const float* __restrict__ W,
             const float* __restrict__ b) {
    __shared__ float2 sX[TB][31];    // [t][kp], pad 31
    __shared__ float2 sW[56][31];    // [j][kp]
    __shared__ float  sB[56];

    const int tid = threadIdx.x;
    const int t0  = blockIdx.x * TB;

    const float2* Wg = (const float2*)W;             // rows of 30 float2
    for (int idx = tid; idx < 56 * 30; idx += 128) {
        int jj = idx / 30, kp = idx - jj * 30;
        sW[jj][kp] = Wg[idx];
    }
    if (tid < 56) sB[tid] = b[tid];
    const float2* Xg = (const float2*)(x + t0 * INW);  // 8B-aligned (240B rows)
    for (int idx = tid; idx < TB * 30; idx += 128) {
        int t = idx / 30, kp = idx - t * 30;
        sX[t][kp] = Xg[idx];
    }
    __syncthreads();

    const int jb = (tid & 7) * 7;        // gate base (7 gates)
    const int tg = tid >> 3;             // 0..15; rows tg, tg+16, ..., tg+112

    float2 acc[8][7];
#pragma unroll
    for (int i = 0; i < 8; i++)
#pragma unroll
        for (int q = 0; q < 7; q++)
            acc[i][q] = make_float2(sB[jb + q], 0.f);

#pragma unroll 3
    for (int kp = 0; kp < 30; kp++) {
        float2 xv[8];
#pragma unroll
        for (int i = 0; i < 8; i++) xv[i] = sX[tg + 16 * i][kp];
#pragma unroll
        for (int q = 0; q < 7; q++) {
            float2 wv = sW[jb + q][kp];
#pragma unroll
            for (int i = 0; i < 8; i++)
                acc[i][q] = ffma2(xv[i], wv, acc[i][q]);
        }
    }

#pragma unroll
    for (int i = 0; i < 8; i++) {
        float* dst = g_xw0s + (t0 + tg + 16 * i) * 56 + jb;
#pragma unroll
        for (int q = 0; q < 7; q++)
            dst[q] = acc[i][q].x + acc[i][q].y;
    }
}

// ---------------- Scan helpers ----------------
__device__ __forceinline__ void mv7(float2& accA, float2& accQ,
                                    const float2 (&wA)[7], const float2 (&wQ)[7],
                                    const float2 (&hp)[7]) {
#pragma unroll
    for (int k = 0; k < 7; k++) {
        accA = ffma2(hp[k], wA[k], accA);
        accQ = ffma2(hp[k], wQ[k], accQ);
    }
}

// All activations via MUFU.TANH (measured error contribution ~1e-6).
__device__ __forceinline__ float act_h(float a, float q, float& c, int kidx,
                                       float kq2, float mm2, float aa2) {
    float sA = fmaf(tanh_ap(a * 0.5f), 0.5f, 0.5f);      // sigmoid (i/f)
    float sQ = fmaf(tanh_ap(q * kq2), mm2, aa2);         // tanh(g) | sigmoid(o)
    float iv = __shfl_sync(FULLM, sA, kidx);
    float fv = __shfl_sync(FULLM, sA, kidx + 14);
    float gv = __shfl_sync(FULLM, sQ, kidx);
    float ov = __shfl_sync(FULLM, sQ, kidx + 14);
    c = fmaf(fv, c, iv * gv);
    return ov * tanh_ap(c);
}

__device__ __forceinline__ void bcast(float2 (&hp)[7], float hn) {
#pragma unroll
    for (int k = 0; k < 7; k++) {
        hp[k].x = __shfl_sync(FULLM, hn, 2 * k);
        hp[k].y = __shfl_sync(FULLM, hn, 2 * k + 1);
    }
}

// ---------------- Kernel 2: chunk-parallel 3-layer LSTM scan + fused output proj ----------------
// Proven configuration (74.2-74.5us measured over 3 runs): block = 1 warp = 1
// chunk of CHUNK=128; 1024 blocks = one resident wave at 246 regs (8/SM cap).
// Chunks > 0 start WARM=32 early from (h,c)=0 (forget-gate contraction).
// ALL weights in registers; h broadcast via SHFL; x via 4-deep FIFO; out fused.
__global__ void __launch_bounds__(32)
lstm_scan_kernel(const float* __restrict__ h0in, const float* __restrict__ c0in,
                 const float* __restrict__ Whh0, const float* __restrict__ bhh0,
                 const float* __restrict__ Wih1, const float* __restrict__ Whh1,
                 const float* __restrict__ bih1, const float* __restrict__ bhh1,
                 const float* __restrict__ Wih2, const float* __restrict__ Whh2,
                 const float* __restrict__ bih2, const float* __restrict__ bhh2,
                 const float* __restrict__ Wlin, const float* __restrict__ blin,
                 float* __restrict__ gout) {
    const int chunk = blockIdx.x;
    const int t0 = chunk * CHUNK;
    const int te = t0 + CHUNK;
    const int s  = (chunk == 0) ? 0 : (t0 - WARM);

    const int  j    = threadIdx.x;
    const int  jj   = (j < 28) ? j : 27;
    const int  kidx = j % 14;
    const bool isg  = (j < 14);
    const float kq2 = isg ? 1.0f : 0.5f;
    const float mm2 = isg ? 1.0f : 0.5f;
    const float aa2 = isg ? 0.0f : 0.5f;

    // weights in registers, packed (w[j][2k], w[j][2k+1])
    float2 w0A[7],  w0Q[7];
    float2 w1iA[7], w1iQ[7], w1hA[7], w1hQ[7];
    float2 w2iA[7], w2iQ[7], w2hA[7], w2hQ[7];
#pragma unroll
    for (int k = 0; k < 7; k++) {
        w0A[k]  = *(const float2*)&Whh0[jj * HH + 2 * k];
        w0Q[k]  = *(const float2*)&Whh0[(jj + 28) * HH + 2 * k];
        w1iA[k] = *(const float2*)&Wih1[jj * HH + 2 * k];
        w1iQ[k] = *(const float2*)&Wih1[(jj + 28) * HH + 2 * k];
        w1hA[k] = *(const float2*)&Whh1[jj * HH + 2 * k];
        w1hQ[k] = *(const float2*)&Whh1[(jj + 28) * HH + 2 * k];
        w2iA[k] = *(const float2*)&Wih2[jj * HH + 2 * k];
        w2iQ[k] = *(const float2*)&Wih2[(jj + 28) * HH + 2 * k];
        w2hA[k] = *(const float2*)&Whh2[jj * HH + 2 * k];
        w2hQ[k] = *(const float2*)&Whh2[(jj + 28) * HH + 2 * k];
    }
    const float b0A = bhh0[jj],            b0Q = bhh0[jj + 28];
    const float b1A = bih1[jj] + bhh1[jj], b1Q = bih1[jj + 28] + bhh1[jj + 28];
    const float b2A = bih2[jj] + bhh2[jj], b2Q = bih2[jj + 28] + bhh2[jj + 28];

    // fused output projection: lane o = j%7 holds Wlin row o
    const int olane = j % 7;
    float2 wl[7];
#pragma unroll
    for (int k = 0; k < 7; k++) wl[k] = *(const float2*)&Wlin[olane * HH + 2 * k];
    const float blv = blin[olane];

    // state: packed replicated h per layer, distributed c
    float2 h0p[7], h1p[7], h2p[7];
    float c0v, c1v, c2v;
    if (chunk == 0) {
#pragma unroll
        for (int k = 0; k < 7; k++) {
            h0p[k] = *(const float2*)&h0in[2 * k];
            h1p[k] = *(const float2*)&h0in[HH + 2 * k];
            h2p[k] = *(const float2*)&h0in[2 * HH + 2 * k];
        }
        c0v = c0in[kidx]; c1v = c0in[HH + kidx]; c2v = c0in[2 * HH + kidx];
    } else {
#pragma unroll
        for (int k = 0; k < 7; k++) {
            h0p[k] = make_float2(0.f, 0.f);
            h1p[k] = make_float2(0.f, 0.f);
            h2p[k] = make_float2(0.f, 0.f);
        }
        c0v = c1v = c2v = 0.f;
    }

    auto do_L0 = [&](float xA, float xQ) -> float {
        float2 aA = make_float2(b0A + xA, 0.f), aQ = make_float2(b0Q + xQ, 0.f);
        mv7(aA, aQ, w0A, w0Q, h0p);
        return act_h(aA.x + aA.y, aQ.x + aQ.y, c0v, kidx, kq2, mm2, aa2);
    };
    auto do_L1 = [&]() -> float {
        float2 aAi = make_float2(b1A, 0.f), aQi = make_float2(b1Q, 0.f);
        float2 aAh = make_float2(0.f, 0.f), aQh = make_float2(0.f, 0.f);
        mv7(aAi, aQi, w1iA, w1iQ, h0p);
        mv7(aAh, aQh, w1hA, w1hQ, h1p);
        float2 aA = fadd2(aAi, aAh), aQ = fadd2(aQi, aQh);
        return act_h(aA.x + aA.y, aQ.x + aQ.y, c1v, kidx, kq2, mm2, aa2);
    };
    auto do_L2 = [&]() -> float {
        float2 aAi = make_float2(b2A, 0.f), aQi = make_float2(b2Q, 0.f);
        float2 aAh = make_float2(0.f, 0.f), aQh = make_float2(0.f, 0.f);
        mv7(aAi, aQi, w2iA, w2iQ, h1p);
        mv7(aAh, aQh, w2hA, w2hQ, h2p);
        float2 aA = fadd2(aAi, aAh), aQ = fadd2(aQi, aQh);
        return act_h(aA.x + aA.y, aQ.x + aQ.y, c2v, kidx, kq2, mm2, aa2);
    };
    // out(t) = relu(relu(h2(t)) @ Wlin^T + blin); h2p must hold replicated h2(t)
    auto do_out = [&](int t) {
        float2 acc = make_float2(blv, 0.f);
#pragma unroll
        for (int k = 0; k < 7; k++) {
            float2 hv = make_float2(fmaxf(h2p[k].x, 0.f), fmaxf(h2p[k].y, 0.f));
            acc = ffma2(hv, wl[k], acc);
        }
        float o = fmaxf(acc.x + acc.y, 0.f);
        if (j < 7) gout[t * 7 + j] = o;
    };

    // one full pipelined iteration at step i; out(i-3) uses h2p BEFORE updates
    auto body = [&](int i, float xA, float xQ) {
        if (i - 3 >= t0) do_out(i - 3);
        float hn0 = do_L0(xA, xQ);
        float hn1 = do_L1();
        float hn2 = do_L2();
        bcast(h0p, hn0);
        bcast(h1p, hn1);
        bcast(h2p, hn2);
    };

    int i = s;

    // ---- Phase A: 2 fill iterations ----
    if (chunk == 0) {
        float xA0 = g_xw0s[jj],      xQ0 = g_xw0s[jj + 28];
        float xA1 = g_xw0s[56 + jj], xQ1 = g_xw0s[56 + jj + 28];
        { float hn0 = do_L0(xA0, xQ0); bcast(h0p, hn0); }
        { float hn1 = do_L1();
          float hn0 = do_L0(xA1, xQ1);
          bcast(h0p, hn0); bcast(h1p, hn1); }
        i = 2;
    } else {
        float xA0 = g_xw0s[s * 56 + jj],        xQ0 = g_xw0s[s * 56 + jj + 28];
        float xA1 = g_xw0s[(s + 1) * 56 + jj],  xQ1 = g_xw0s[(s + 1) * 56 + jj + 28];
        body(i, xA0, xQ0);       // i-3 < t0: no out-store
        body(i + 1, xA1, xQ1);
        i = s + 2;
    }

    // ---- prime the 4-deep x FIFO for steps i..i+3 ----
    float xbA[4], xbQ[4];
#pragma unroll
    for (int u = 0; u < 4; u++) {
        xbA[u] = g_xw0s[(i + u) * 56 + jj];
        xbQ[u] = g_xw0s[(i + u) * 56 + jj + 28];
    }

    // ---- main loop: unrolled x4, prefetch distance 4 ----
#pragma unroll 1
    for (; i + 4 <= te; i += 4) {
#pragma unroll
        for (int u = 0; u < 4; u++) {
            float xA = xbA[u], xQ = xbQ[u];
            xbA[u] = g_xw0s[(i + u + 4) * 56 + jj];        // prefetch i+u+4
            xbQ[u] = g_xw0s[(i + u + 4) * 56 + jj + 28];
            body(i + u, xA, xQ);
        }
    }
    // remainder (<= 3 iters)
#pragma unroll 3
    for (int u = 0; i < te; i++, u++) {
        body(i, xbA[u], xbQ[u]);
    }

    // ---- epilogues: drain L1, L2, out (state lives in registers) ----
    {   // out(te-3), L1(te-1), L2(te-2)
        do_out(te - 3);
        float hn1 = do_L1();
        float hn2 = do_L2();
        bcast(h1p, hn1);
        bcast(h2p, hn2);
    }
    {   // out(te-2), L2(te-1)
        do_out(te - 2);
        float hn2 = do_L2();
        bcast(h2p, hn2);
    }
    {   // out(te-1)
        do_out(te - 1);
    }
}

extern "C" void kernel_launch(void* const* d_in, const int* in_sizes, int n_in,
                              void* d_out, int out_size) {
    const float* x    = (const float*)d_in[0];
    const float* h0   = (const float*)d_in[1];
    const float* c0   = (const float*)d_in[2];
    const float* Wih0 = (const float*)d_in[3];
    const float* Whh0 = (const float*)d_in[4];
    const float* bih0 = (const float*)d_in[5];
    const float* bhh0 = (const float*)d_in[6];
    const float* Wih1 = (const float*)d_in[7];
    const float* Whh1 = (const float*)d_in[8];
    const float* bih1 = (const float*)d_in[9];
    const float* bhh1 = (const float*)d_in[10];
    const float* Wih2 = (const float*)d_in[11];
    const float* Whh2 = (const float*)d_in[12];
    const float* bih2 = (const float*)d_in[13];
    const float* bhh2 = (const float*)d_in[14];
    const float* Wlin = (const float*)d_in[15];
    const float* blin = (const float*)d_in[16];
    float* out = (float*)d_out;

    xproj_kernel<<<TT / TB, 128>>>(x, Wih0, bih0);
    lstm_scan_kernel<<<NCH, 32>>>(h0, c0, Whh0, bhh0,
                                  Wih1, Whh1, bih1, bhh1,
                                  Wih2, Whh2, bih2, bhh2,
                                  Wlin, blin, out);
}